// round 10
// baseline (speedup 1.0000x reference)
#include <cuda_runtime.h>
#include <math.h>

#define NUM_RADIUS 15
#define NUM_ANGLE 48
#define EMB 32
#define NUM_ACTIONS 4
#define TPB 256

// Fast atan2 with provable accuracy:
//   t = min/max in [0,1]; half-angle reduce u = t/(1+sqrt(1+t^2)) in [0, 0.4142];
//   Taylor series of atan(u) through u^13 (truncation <= u^15/15 ~ 1.2e-7 rad);
//   atan(t) = 2*atan(u). Total error ~1e-6 rad including division rounding.
__device__ __forceinline__ float fast_atan2f(float y, float x) {
    float ax = fabsf(x), ay = fabsf(y);
    float mn = fminf(ax, ay), mx = fmaxf(ax, ay);
    float t = __fdividef(mn, mx);                          // [0,1]
    float r = sqrtf(fmaf(t, t, 1.0f));                     // [1, 1.414]
    float u = __fdividef(t, 1.0f + r);                     // [0, 0.4142]
    float s = u * u;
    float p = 0.07692307693f;                 //  1/13
    p = fmaf(p, s, -0.09090909091f);          // -1/11
    p = fmaf(p, s,  0.11111111111f);          //  1/9
    p = fmaf(p, s, -0.14285714286f);          // -1/7
    p = fmaf(p, s,  0.2f);                    //  1/5
    p = fmaf(p, s, -0.33333333333f);          // -1/3
    float atu = fmaf(p * s, u, u);            // atan(u)
    float a = 2.0f * atu;                     // atan(t)
    if (ay > ax) a = 1.57079632679f - a;
    if (x < 0.0f) a = 3.14159265359f - a;
    return (y < 0.0f) ? -a : a;
}

__device__ __forceinline__ float4 process_row(float axp, float azp, float pose,
                                              float gx, float gz,
                                              const float* __restrict__ sLR,
                                              const float* __restrict__ sLA) {
    float dx = gx - axp;
    float dz = gz - azp;

    // radius bucket
    float radius = sqrtf(fmaf(dx, dx, dz * dz));
    int r_idx = (int)(radius * 0.2f);
    r_idx = max(0, min(r_idx, NUM_RADIUS - 1));

    // angle bucket: match reference rounding (separate mul then sub, no fma)
    float deg = __fmul_rn(fast_atan2f(dz, dx), 57.29577951308232f);
    float dtg = __fsub_rn(90.0f, deg);
    float f = __fsub_rn(dtg, pose);
    float ad = fmaf(-360.0f, floorf(f * 0.0027777778f), f);
    ad = fminf(fmaxf(ad, 0.0f), 359.99997f);
    int t_idx = (int)(ad * 0.13333334f);
    t_idx = max(0, min(t_idx, NUM_ANGLE - 1));

    const float* lr = &sLR[r_idx * NUM_ACTIONS];
    const float* la = &sLA[t_idx * NUM_ACTIONS];
    float l0 = lr[0] + la[0];
    float l1 = lr[1] + la[1];
    float l2 = lr[2] + la[2];
    float l3 = lr[3] + la[3];

    float m = fmaxf(fmaxf(l0, l1), fmaxf(l2, l3));
    float e0 = __expf(l0 - m);
    float e1 = __expf(l1 - m);
    float e2 = __expf(l2 - m);
    float e3 = __expf(l3 - m);
    float lse = __logf(e0 + e1 + e2 + e3) + m;

    return make_float4(l0 - lse, l1 - lse, l2 - lse, l3 - lse);
}

__global__ void __launch_bounds__(TPB)
goal_position_fused(const float4* __restrict__ agent4,  // [B,3] as float4s
                    const float4* __restrict__ goal4,   // [B,2] as float4s
                    float4* __restrict__ out,           // [B,4]
                    int n4,                              // n/4
                    const float* __restrict__ radius_table,
                    const float* __restrict__ angle_table,
                    const float* __restrict__ W,
                    const float* __restrict__ b) {
    __shared__ float sW[2 * EMB * NUM_ACTIONS];        // 1 KB
    __shared__ float sLR[NUM_RADIUS * NUM_ACTIONS];    // 60 floats
    __shared__ float sLA[NUM_ANGLE * NUM_ACTIONS];     // 192 floats

    const int t = threadIdx.x;

    // ---- Prologue: build the two tiny logit tables (replaces the separate
    // precompute launch; inputs L2-resident after the first wave) ----
    if (t < 2 * EMB * NUM_ACTIONS) sW[t] = W[t];
    __syncthreads();

    if (t < NUM_RADIUS * NUM_ACTIONS) {                 // 60 dots
        int row = t >> 2, a = t & 3;
        float s = 0.0f;
        #pragma unroll
        for (int e = 0; e < EMB; e++)
            s += __ldg(&radius_table[row * EMB + e]) * sW[e * NUM_ACTIONS + a];
        sLR[t] = s;
    } else if (t < (NUM_RADIUS + NUM_ANGLE) * NUM_ACTIONS) {  // 192 dots
        int k = t - NUM_RADIUS * NUM_ACTIONS;
        int row = k >> 2, a = k & 3;
        float s = __ldg(&b[a]);
        #pragma unroll
        for (int e = 0; e < EMB; e++)
            s += __ldg(&angle_table[row * EMB + e]) * sW[(EMB + e) * NUM_ACTIONS + a];
        sLA[k] = s;
    }
    __syncthreads();

    // ---- Main loop: EXACT R3 structure (measured best): 4 rows/thread,
    // 5 batched plain LDG.128, scalar LDS table reads, inline softmax ----
    int i = blockIdx.x * TPB + t;
    if (i >= n4) return;

    float4 a0 = agent4[3 * i + 0];   // x0 z0 p0 x1
    float4 a1 = agent4[3 * i + 1];   // z1 p1 x2 z2
    float4 a2 = agent4[3 * i + 2];   // p2 x3 z3 p3
    float4 g0 = goal4[2 * i + 0];    // gx0 gz0 gx1 gz1
    float4 g1 = goal4[2 * i + 1];    // gx2 gz2 gx3 gz3

    float4 o0 = process_row(a0.x, a0.y, a0.z, g0.x, g0.y, sLR, sLA);
    float4 o1 = process_row(a0.w, a1.x, a1.y, g0.z, g0.w, sLR, sLA);
    float4 o2 = process_row(a1.z, a1.w, a2.x, g1.x, g1.y, sLR, sLA);
    float4 o3 = process_row(a2.y, a2.z, a2.w, g1.z, g1.w, sLR, sLA);

    out[4 * i + 0] = o0;
    out[4 * i + 1] = o1;
    out[4 * i + 2] = o2;
    out[4 * i + 3] = o3;
}

extern "C" void kernel_launch(void* const* d_in, const int* in_sizes, int n_in,
                              void* d_out, int out_size) {
    const float* agent = (const float*)d_in[0];   // [B,3]
    const float* goal = (const float*)d_in[1];    // [B,2]
    const float* radius_table = (const float*)d_in[2];
    const float* angle_table = (const float*)d_in[3];
    const float* W = (const float*)d_in[4];
    const float* b = (const float*)d_in[5];

    int n = in_sizes[0] / 3;    // B = 2,000,000 (divisible by 4)
    int n4 = n / 4;

    int blocks = (n4 + TPB - 1) / TPB;   // 1954, non-persistent (R3 style)
    goal_position_fused<<<blocks, TPB>>>((const float4*)agent,
                                         (const float4*)goal,
                                         (float4*)d_out, n4,
                                         radius_table, angle_table, W, b);
}

// round 11
// speedup vs baseline: 1.7733x; 1.7733x over previous
#include <cuda_runtime.h>
#include <math.h>

#define NUM_RADIUS 15
#define NUM_ANGLE 48
#define EMB 32
#define NUM_ACTIONS 4
#define TPB 256

// LR[r][a] = sum_e radius_table[r][e] * W[e][a]
// LA[t][a] = sum_e angle_table[t][e]  * W[32+e][a] + b[a]
__device__ float g_LR[NUM_RADIUS * NUM_ACTIONS];
__device__ float g_LA[NUM_ANGLE * NUM_ACTIONS];

// Warp-per-output precompute: 252 outputs, one warp each (32 blocks x 8 warps).
// Lane e holds table[row][e] * W[...][a]; 5-step shuffle reduction.
__global__ void __launch_bounds__(TPB)
precompute_tables_kernel(const float* __restrict__ radius_table,
                         const float* __restrict__ angle_table,
                         const float* __restrict__ W,
                         const float* __restrict__ b) {
    int warp = (blockIdx.x * TPB + threadIdx.x) >> 5;   // 0..255
    int lane = threadIdx.x & 31;
    const int NLR = NUM_RADIUS * NUM_ACTIONS;   // 60
    const int NLA = NUM_ANGLE * NUM_ACTIONS;    // 192

    float v = 0.0f;
    bool is_lr = warp < NLR;
    bool is_la = !is_lr && warp < NLR + NLA;
    if (is_lr) {
        int row = warp >> 2, a = warp & 3;
        v = radius_table[row * EMB + lane] * W[lane * NUM_ACTIONS + a];
    } else if (is_la) {
        int k = warp - NLR;
        int row = k >> 2, a = k & 3;
        v = angle_table[row * EMB + lane] * W[(EMB + lane) * NUM_ACTIONS + a];
        if (lane == 0) v += b[a];
    }
    #pragma unroll
    for (int off = 16; off > 0; off >>= 1)
        v += __shfl_down_sync(0xffffffffu, v, off);

    if (lane == 0) {
        if (is_lr) g_LR[warp] = v;
        else if (is_la) g_LA[warp - NLR] = v;
    }
}

// Fast atan2 with provable accuracy:
//   t = min/max in [0,1]; half-angle reduce u = t/(1+sqrt(1+t^2)) in [0, 0.4142];
//   Taylor series of atan(u) through u^13 (truncation <= u^15/15 ~ 1.2e-7);
//   atan(t) = 2*atan(u). Total error ~1e-6 rad including division rounding.
__device__ __forceinline__ float fast_atan2f(float y, float x) {
    float ax = fabsf(x), ay = fabsf(y);
    float mn = fminf(ax, ay), mx = fmaxf(ax, ay);
    float t = __fdividef(mn, mx);                          // [0,1]
    float r = sqrtf(fmaf(t, t, 1.0f));                     // [1, 1.414]
    float u = __fdividef(t, 1.0f + r);                     // [0, 0.4142]
    float s = u * u;
    float p = 0.07692307693f;                 //  1/13
    p = fmaf(p, s, -0.09090909091f);          // -1/11
    p = fmaf(p, s,  0.11111111111f);          //  1/9
    p = fmaf(p, s, -0.14285714286f);          // -1/7
    p = fmaf(p, s,  0.2f);                    //  1/5
    p = fmaf(p, s, -0.33333333333f);          // -1/3
    float atu = fmaf(p * s, u, u);            // atan(u)
    float a = 2.0f * atu;                     // atan(t)
    if (ay > ax) a = 1.57079632679f - a;
    if (x < 0.0f) a = 3.14159265359f - a;
    return (y < 0.0f) ? -a : a;
}

__device__ __forceinline__ float4 process_row(float axp, float azp, float pose,
                                              float gx, float gz,
                                              const float* __restrict__ sLR,
                                              const float* __restrict__ sLA) {
    float dx = gx - axp;
    float dz = gz - azp;

    // radius bucket
    float radius = sqrtf(fmaf(dx, dx, dz * dz));
    int r_idx = (int)(radius * 0.2f);
    r_idx = max(0, min(r_idx, NUM_RADIUS - 1));

    // angle bucket: match reference rounding (separate mul then sub, no fma)
    float deg = __fmul_rn(fast_atan2f(dz, dx), 57.29577951308232f);
    float dtg = __fsub_rn(90.0f, deg);
    float f = __fsub_rn(dtg, pose);
    float ad = fmaf(-360.0f, floorf(f * 0.0027777778f), f);
    ad = fminf(fmaxf(ad, 0.0f), 359.99997f);
    int t_idx = (int)(ad * 0.13333334f);
    t_idx = max(0, min(t_idx, NUM_ANGLE - 1));

    const float* lr = &sLR[r_idx * NUM_ACTIONS];
    const float* la = &sLA[t_idx * NUM_ACTIONS];
    float l0 = lr[0] + la[0];
    float l1 = lr[1] + la[1];
    float l2 = lr[2] + la[2];
    float l3 = lr[3] + la[3];

    float m = fmaxf(fmaxf(l0, l1), fmaxf(l2, l3));
    float e0 = __expf(l0 - m);
    float e1 = __expf(l1 - m);
    float e2 = __expf(l2 - m);
    float e3 = __expf(l3 - m);
    float lse = __logf(e0 + e1 + e2 + e3) + m;

    return make_float4(l0 - lse, l1 - lse, l2 - lse, l3 - lse);
}

__global__ void __launch_bounds__(TPB)
goal_position_kernel(const float4* __restrict__ agent4,  // [B,3] as float4s
                     const float4* __restrict__ goal4,   // [B,2] as float4s
                     float4* __restrict__ out,           // [B,4]
                     int n4) {                            // n/4
    __shared__ float sLR[NUM_RADIUS * NUM_ACTIONS];
    __shared__ float sLA[NUM_ANGLE * NUM_ACTIONS];
    int t = threadIdx.x;
    if (t < NUM_RADIUS * NUM_ACTIONS) sLR[t] = g_LR[t];
    if (t < NUM_ANGLE * NUM_ACTIONS) sLA[t] = g_LA[t];
    __syncthreads();

    int i = blockIdx.x * blockDim.x + t;
    if (i >= n4) return;

    // 4 rows per thread: 12 agent floats, 8 goal floats, 16 out floats
    float4 a0 = agent4[3 * i + 0];   // x0 z0 p0 x1
    float4 a1 = agent4[3 * i + 1];   // z1 p1 x2 z2
    float4 a2 = agent4[3 * i + 2];   // p2 x3 z3 p3
    float4 g0 = goal4[2 * i + 0];    // gx0 gz0 gx1 gz1
    float4 g1 = goal4[2 * i + 1];    // gx2 gz2 gx3 gz3

    float4 o0 = process_row(a0.x, a0.y, a0.z, g0.x, g0.y, sLR, sLA);
    float4 o1 = process_row(a0.w, a1.x, a1.y, g0.z, g0.w, sLR, sLA);
    float4 o2 = process_row(a1.z, a1.w, a2.x, g1.x, g1.y, sLR, sLA);
    float4 o3 = process_row(a2.y, a2.z, a2.w, g1.z, g1.w, sLR, sLA);

    out[4 * i + 0] = o0;
    out[4 * i + 1] = o1;
    out[4 * i + 2] = o2;
    out[4 * i + 3] = o3;
}

extern "C" void kernel_launch(void* const* d_in, const int* in_sizes, int n_in,
                              void* d_out, int out_size) {
    const float* agent = (const float*)d_in[0];   // [B,3]
    const float* goal = (const float*)d_in[1];    // [B,2]
    const float* radius_table = (const float*)d_in[2];
    const float* angle_table = (const float*)d_in[3];
    const float* W = (const float*)d_in[4];
    const float* b = (const float*)d_in[5];

    int n = in_sizes[0] / 3;    // B = 2,000,000 (divisible by 4)
    int n4 = n / 4;

    // 252 warp-sized dot products across 32 blocks (one short wave)
    precompute_tables_kernel<<<32, TPB>>>(radius_table, angle_table, W, b);

    int blocks = (n4 + TPB - 1) / TPB;   // 1954
    goal_position_kernel<<<blocks, TPB>>>((const float4*)agent,
                                          (const float4*)goal,
                                          (float4*)d_out, n4);
}